// round 2
// baseline (speedup 1.0000x reference)
#include <cuda_runtime.h>
#include <math.h>

// Problem constants: B=32, S=64, E=256, H=4, D=64
#define NROWS 2048        // B*S
#define EDIM  256
#define NQKV  768
#define NH    4

#define TM 64
#define TN 64
#define KC 128
#define AS_LD 65          // padded lead dim for transposed A tile

// Scratch (allocation-free rule: __device__ globals)
__device__ float g_EW [EDIM * NQKV];   // [j][n] = exp(W_{q|k|v}[n mod 256][j])
__device__ float g_EWo[EDIM * EDIM];   // [j][n] = exp(Wo[n][j])
__device__ float g_Y  [NROWS * NQKV];  // q,k: raw sums * exp(bias); v: log(sum)+bv
__device__ float g_EO [NROWS * EDIM];  // exp(attention output)

// ---------------------------------------------------------------------------
// Preprocess: build transposed exp(W) matrices.
// ---------------------------------------------------------------------------
__global__ void k_pre(const float* __restrict__ Wq, const float* __restrict__ Wk,
                      const float* __restrict__ Wv, const float* __restrict__ Wo)
{
    int idx = blockIdx.x * blockDim.x + threadIdx.x;
    if (idx < EDIM * NQKV) {
        int j = idx / NQKV;
        int n = idx % NQKV;
        const float* W = (n < 256) ? Wq : ((n < 512) ? Wk : Wv);
        int i = n & 255;
        g_EW[idx] = __expf(W[i * EDIM + j]);
    } else {
        int t = idx - EDIM * NQKV;
        if (t < EDIM * EDIM) {
            int j = t / EDIM;
            int n = t % EDIM;
            g_EWo[t] = __expf(Wo[n * EDIM + j]);
        }
    }
}

// ---------------------------------------------------------------------------
// Tiled fp32 GEMM: C[M x N] = A[M x 256] * B[256 x N]
//   mode 0: A elements pass through exp() during smem load (A = x).
//           epilogue: cols [0,256)   -> acc * exp(bq[col])        (exp(q))
//                     cols [256,512) -> acc * exp(bk[col-256])    (exp(k))
//                     cols [512,768) -> log(acc) + bv[col-512]    (v values)
//   mode 1: A loaded as-is (A = g_EO). epilogue: log(acc) + bo[col]
// ---------------------------------------------------------------------------
__global__ void k_gemm(const float* __restrict__ A, const float* __restrict__ B,
                       float* __restrict__ C, int ldb, int ldc,
                       const float* __restrict__ b0, const float* __restrict__ b1,
                       const float* __restrict__ b2, int mode)
{
    extern __shared__ float sm[];
    float* As = sm;                 // [KC][AS_LD]  (k-major, transposed)
    float* Bs = sm + KC * AS_LD;    // [KC][TN]

    const int tx = threadIdx.x & 15;
    const int ty = threadIdx.x >> 4;
    const int m0 = blockIdx.y * TM;
    const int n0 = blockIdx.x * TN;

    float acc[4][4] = {};

    for (int kc = 0; kc < 256; kc += KC) {
        // --- load A tile (TM x KC) transposed into As[k][row], fusing exp ---
        for (int v = threadIdx.x; v < (TM * KC) / 4; v += 256) {
            int row = v >> 5;              // / (KC/4)
            int k4  = v & 31;
            float4 a = *(const float4*)&A[(m0 + row) * 256 + kc + k4 * 4];
            if (mode == 0) {
                a.x = __expf(a.x); a.y = __expf(a.y);
                a.z = __expf(a.z); a.w = __expf(a.w);
            }
            As[(k4 * 4 + 0) * AS_LD + row] = a.x;
            As[(k4 * 4 + 1) * AS_LD + row] = a.y;
            As[(k4 * 4 + 2) * AS_LD + row] = a.z;
            As[(k4 * 4 + 3) * AS_LD + row] = a.w;
        }
        // --- load B tile (KC x TN) ---
        for (int v = threadIdx.x; v < (KC * TN) / 4; v += 256) {
            int k  = v >> 4;               // / (TN/4)
            int c4 = v & 15;
            *(float4*)&Bs[k * TN + c4 * 4] =
                *(const float4*)&B[(kc + k) * ldb + n0 + c4 * 4];
        }
        __syncthreads();

        #pragma unroll 8
        for (int k = 0; k < KC; ++k) {
            const float* ar = &As[k * AS_LD + 4 * ty];
            float a0 = ar[0], a1 = ar[1], a2 = ar[2], a3 = ar[3];
            float4 bv4 = *(const float4*)&Bs[k * TN + 4 * tx];
            acc[0][0] += a0 * bv4.x; acc[0][1] += a0 * bv4.y;
            acc[0][2] += a0 * bv4.z; acc[0][3] += a0 * bv4.w;
            acc[1][0] += a1 * bv4.x; acc[1][1] += a1 * bv4.y;
            acc[1][2] += a1 * bv4.z; acc[1][3] += a1 * bv4.w;
            acc[2][0] += a2 * bv4.x; acc[2][1] += a2 * bv4.y;
            acc[2][2] += a2 * bv4.z; acc[2][3] += a2 * bv4.w;
            acc[3][0] += a3 * bv4.x; acc[3][1] += a3 * bv4.y;
            acc[3][2] += a3 * bv4.z; acc[3][3] += a3 * bv4.w;
        }
        __syncthreads();
    }

    // --- epilogue ---
    #pragma unroll
    for (int r = 0; r < 4; ++r) {
        int grow = m0 + 4 * ty + r;
        #pragma unroll
        for (int c = 0; c < 4; ++c) {
            int gcol = n0 + 4 * tx + c;
            float v = acc[r][c];
            float o;
            if (mode == 0) {
                if (gcol < 256)      o = v * __expf(b0[gcol]);
                else if (gcol < 512) o = v * __expf(b1[gcol - 256]);
                else                 o = __logf(v) + b2[gcol - 512];
            } else {
                o = __logf(v) + b0[gcol];
            }
            C[grow * ldc + gcol] = o;
        }
    }
}

// ---------------------------------------------------------------------------
// Attention: one CTA per (b, h).
//   p[s][d] = exp(q)[s,d] * exp(k)[s,d]   (== exp(q+k), biases folded in)
//   attn    = p / rowsum(p)
//   out[s,e] = sum_d attn[s,d] * v[d,e]   (v already = log(Sv)+bv in g_Y)
//   g_EO = exp(out)
// ---------------------------------------------------------------------------
__global__ void k_attn()
{
    __shared__ float P[64][65];
    __shared__ float V[64][68];
    __shared__ float inv[64];

    const int h = blockIdx.x;
    const int b = blockIdx.y;
    const int tid = threadIdx.x;

    for (int i = tid; i < 4096; i += 256) {
        int s = i >> 6, d = i & 63;
        const float* yr = &g_Y[(b * 64 + s) * NQKV + h * 64 + d];
        P[s][d] = yr[0] * yr[256];
    }
    for (int i = tid; i < 4096; i += 256) {
        int d = i >> 6, e = i & 63;
        // v values already hold log(Sv) + bv — use directly (no second log!)
        V[d][e] = g_Y[(b * 64 + d) * NQKV + 512 + h * 64 + e];
    }
    __syncthreads();

    if (tid < 64) {
        float s = 0.f;
        #pragma unroll
        for (int j = 0; j < 64; ++j) s += P[tid][j];
        inv[tid] = 1.0f / s;
    }
    __syncthreads();

    const int tx = tid & 15;
    const int ty = tid >> 4;
    float acc[4][4] = {};

    #pragma unroll 4
    for (int d = 0; d < 64; ++d) {
        float p0 = P[4 * ty + 0][d];
        float p1 = P[4 * ty + 1][d];
        float p2 = P[4 * ty + 2][d];
        float p3 = P[4 * ty + 3][d];
        float4 v4 = *(const float4*)&V[d][4 * tx];
        acc[0][0] += p0 * v4.x; acc[0][1] += p0 * v4.y;
        acc[0][2] += p0 * v4.z; acc[0][3] += p0 * v4.w;
        acc[1][0] += p1 * v4.x; acc[1][1] += p1 * v4.y;
        acc[1][2] += p1 * v4.z; acc[1][3] += p1 * v4.w;
        acc[2][0] += p2 * v4.x; acc[2][1] += p2 * v4.y;
        acc[2][2] += p2 * v4.z; acc[2][3] += p2 * v4.w;
        acc[3][0] += p3 * v4.x; acc[3][1] += p3 * v4.y;
        acc[3][2] += p3 * v4.z; acc[3][3] += p3 * v4.w;
    }

    #pragma unroll
    for (int r = 0; r < 4; ++r) {
        float iv = inv[4 * ty + r];
        int grow = b * 64 + 4 * ty + r;
        #pragma unroll
        for (int c = 0; c < 4; ++c) {
            float o = acc[r][c] * iv;
            g_EO[grow * EDIM + h * 64 + 4 * tx + c] = __expf(o);
        }
    }
}

// ---------------------------------------------------------------------------
extern "C" void kernel_launch(void* const* d_in, const int* in_sizes, int n_in,
                              void* d_out, int out_size)
{
    const float* x  = (const float*)d_in[0];
    const float* Wq = (const float*)d_in[1];
    const float* bq = (const float*)d_in[2];
    const float* Wk = (const float*)d_in[3];
    const float* bk = (const float*)d_in[4];
    const float* Wv = (const float*)d_in[5];
    const float* bv = (const float*)d_in[6];
    const float* Wo = (const float*)d_in[7];
    const float* bo = (const float*)d_in[8];
    float* out = (float*)d_out;

    const int smem_gemm = (KC * AS_LD + KC * TN) * sizeof(float); // 66048 B
    cudaFuncSetAttribute(k_gemm, cudaFuncAttributeMaxDynamicSharedMemorySize, smem_gemm);

    float* Y  = nullptr; cudaGetSymbolAddress((void**)&Y,  g_Y);
    float* EW = nullptr; cudaGetSymbolAddress((void**)&EW, g_EW);
    float* EWo= nullptr; cudaGetSymbolAddress((void**)&EWo,g_EWo);
    float* EO = nullptr; cudaGetSymbolAddress((void**)&EO, g_EO);

    // 1. preprocess weights
    k_pre<<<(EDIM * NQKV + EDIM * EDIM + 255) / 256, 256>>>(Wq, Wk, Wv, Wo);

    // 2. fused QKV: Y[2048 x 768] = exp(x) @ EW ; epilogue per-column
    {
        dim3 grid(NQKV / TN, NROWS / TM);   // (12, 32)
        k_gemm<<<grid, 256, smem_gemm>>>(x, EW, Y, NQKV, NQKV, bq, bk, bv, 0);
    }

    // 3. attention per (b, h)
    {
        dim3 grid(NH, 32);
        k_attn<<<grid, 256>>>();
    }

    // 4. output projection: out = log(EO @ EWo) + bo
    {
        dim3 grid(EDIM / TN, NROWS / TM);   // (4, 32)
        k_gemm<<<grid, 256, smem_gemm>>>(EO, EWo, out, EDIM, EDIM, bo, nullptr, nullptr, 1);
    }
}

// round 4
// speedup vs baseline: 1.2255x; 1.2255x over previous
#include <cuda_runtime.h>
#include <cuda_bf16.h>
#include <cstdint>
#include <math.h>

// Problem constants: B=32, S=64, E=256, H=4, D=64
#define NROWS 2048
#define EDIM  256
#define NQKV  768
#define NH    4

// ---------------- scratch (__device__ globals, no allocs) -------------------
__device__ __nv_bfloat16 g_Ahi[NROWS * EDIM], g_Alo[NROWS * EDIM];   // exp(x) split
__device__ __nv_bfloat16 g_Bhi[NQKV * EDIM],  g_Blo[NQKV * EDIM];    // exp(Wqkv) [n][k]
__device__ __nv_bfloat16 g_Chi[EDIM * EDIM],  g_Clo[EDIM * EDIM];    // exp(Wo)   [n][k]
__device__ __nv_bfloat16 g_EOhi[NROWS * EDIM], g_EOlo[NROWS * EDIM]; // exp(attn out)
__device__ float g_Y[NROWS * NQKV];  // q,k: sum*exp(bias); v: log(sum)+bv

// ---------------- warp MMA helpers (base ISA, legal on sm_103) --------------
__device__ __forceinline__ uint32_t smem_u32(const void* p) {
    uint32_t a;
    asm("{ .reg .u64 t; cvta.to.shared.u64 t, %1; cvt.u32.u64 %0, t; }"
        : "=r"(a) : "l"(p));
    return a;
}
__device__ __forceinline__ void ldsm_x4(uint32_t* r, uint32_t addr) {
    asm volatile("ldmatrix.sync.aligned.m8n8.x4.shared.b16 {%0,%1,%2,%3}, [%4];"
                 : "=r"(r[0]), "=r"(r[1]), "=r"(r[2]), "=r"(r[3]) : "r"(addr));
}
__device__ __forceinline__ void mma16816(float* d, const uint32_t* a,
                                         uint32_t b0, uint32_t b1) {
    asm volatile(
        "mma.sync.aligned.m16n8k16.row.col.f32.bf16.bf16.f32 "
        "{%0,%1,%2,%3}, {%4,%5,%6,%7}, {%8,%9}, {%0,%1,%2,%3};"
        : "+f"(d[0]), "+f"(d[1]), "+f"(d[2]), "+f"(d[3])
        : "r"(a[0]), "r"(a[1]), "r"(a[2]), "r"(a[3]), "r"(b0), "r"(b1));
}

// ---------------------------------------------------------------------------
// Prep: exp() everything, split into bf16 hi/lo pairs.
// ---------------------------------------------------------------------------
__global__ void k_prep(const float* __restrict__ x,
                       const float* __restrict__ Wq, const float* __restrict__ Wk,
                       const float* __restrict__ Wv, const float* __restrict__ Wo)
{
    int i = blockIdx.x * blockDim.x + threadIdx.x;
    float v; __nv_bfloat16 *hi, *lo; int idx;
    if (i < NROWS * EDIM) {
        idx = i; v = __expf(x[i]); hi = g_Ahi; lo = g_Alo;
    } else if (i < NROWS * EDIM + NQKV * EDIM) {
        idx = i - NROWS * EDIM;
        int n = idx / EDIM, k = idx - n * EDIM;
        const float* W = (n < 256) ? Wq : ((n < 512) ? Wk : Wv);
        v = __expf(W[(n & 255) * EDIM + k]); hi = g_Bhi; lo = g_Blo;
    } else {
        idx = i - NROWS * EDIM - NQKV * EDIM;
        v = __expf(Wo[idx]); hi = g_Chi; lo = g_Clo;
    }
    __nv_bfloat16 h = __float2bfloat16(v);
    hi[idx] = h;
    lo[idx] = __float2bfloat16(v - __bfloat162float(h));
}

// ---------------------------------------------------------------------------
// bf16x3 GEMM via mma.sync: C[m,n] = sum_k A[m,k]*B[n,k] (fp32 accum).
//   CTA 128x64, warp 32x32, K=256 in 4 chunks of 64.
//   mode 0 epilogue: n<256 -> acc*exp(bq), n<512 -> acc*exp(bk), else log+bv
//   mode 1 epilogue: log(acc)+bo
// ---------------------------------------------------------------------------
#define LDA 72                       // padded row stride (bf16 elems), 144 B
#define LDB 72
#define OFF_AHI 0
#define OFF_ALO (128 * LDA * 2)      // 18432
#define OFF_BHI (OFF_ALO + 128 * LDA * 2)   // 36864
#define OFF_BLO (OFF_BHI + 64 * LDB * 2)    // 46080
#define SM_TOT  (OFF_BLO + 64 * LDB * 2)    // 55296

__global__ void __launch_bounds__(256, 2) k_tgemm(
    const __nv_bfloat16* __restrict__ Ahi, const __nv_bfloat16* __restrict__ Alo,
    const __nv_bfloat16* __restrict__ Bhi, const __nv_bfloat16* __restrict__ Blo,
    float* __restrict__ C, int ldc,
    const float* __restrict__ b0, const float* __restrict__ b1,
    const float* __restrict__ b2, int mode)
{
    extern __shared__ char smem[];
    __nv_bfloat16* sAhi = (__nv_bfloat16*)(smem + OFF_AHI);
    __nv_bfloat16* sAlo = (__nv_bfloat16*)(smem + OFF_ALO);
    __nv_bfloat16* sBhi = (__nv_bfloat16*)(smem + OFF_BHI);
    __nv_bfloat16* sBlo = (__nv_bfloat16*)(smem + OFF_BLO);

    const int tid  = threadIdx.x;
    const int lane = tid & 31;
    const int warp = tid >> 5;
    const int wm   = (warp & 3) * 32;    // warp row offset in CTA tile
    const int wn   = (warp >> 2) * 32;   // warp col offset
    const int m0 = blockIdx.y * 128;
    const int n0 = blockIdx.x * 64;

    // ldmatrix base byte-offsets (within each smem region)
    uint32_t aOff[2], bOff[2];
    #pragma unroll
    for (int mf = 0; mf < 2; ++mf)
        aOff[mf] = ((wm + mf * 16 + (lane & 15)) * LDA + (lane >> 4) * 8) * 2;
    #pragma unroll
    for (int h = 0; h < 2; ++h)
        bOff[h] = ((wn + h * 16 + (lane >> 4) * 8 + (lane & 7)) * LDB
                   + ((lane >> 3) & 1) * 8) * 2;

    const uint32_t sbase = smem_u32(smem);

    float acc[2][4][4];
    #pragma unroll
    for (int mf = 0; mf < 2; ++mf)
        #pragma unroll
        for (int nf = 0; nf < 4; ++nf)
            #pragma unroll
            for (int j = 0; j < 4; ++j) acc[mf][nf][j] = 0.f;

    for (int kc = 0; kc < 4; ++kc) {
        const int kb = kc * 64;
        // ---- fill A (128 x 64) hi/lo : 1024 uint4 per array -------------
        for (int c = tid; c < 1024; c += 256) {
            int r = c >> 3, k8 = (c & 7) * 8;
            *(uint4*)&sAhi[r * LDA + k8] = *(const uint4*)&Ahi[(m0 + r) * EDIM + kb + k8];
            *(uint4*)&sAlo[r * LDA + k8] = *(const uint4*)&Alo[(m0 + r) * EDIM + kb + k8];
        }
        // ---- fill B (64 x 64) hi/lo : 512 uint4 per array ---------------
        for (int c = tid; c < 512; c += 256) {
            int r = c >> 3, k8 = (c & 7) * 8;
            *(uint4*)&sBhi[r * LDB + k8] = *(const uint4*)&Bhi[(n0 + r) * EDIM + kb + k8];
            *(uint4*)&sBlo[r * LDB + k8] = *(const uint4*)&Blo[(n0 + r) * EDIM + kb + k8];
        }
        __syncthreads();

        #pragma unroll
        for (int ks = 0; ks < 4; ++ks) {
            const uint32_t kByte = ks * 32;  // 16 bf16
            uint32_t ah[2][4], al[2][4], bh[2][4], bl[2][4];
            #pragma unroll
            for (int mf = 0; mf < 2; ++mf) {
                ldsm_x4(ah[mf], sbase + OFF_AHI + aOff[mf] + kByte);
                ldsm_x4(al[mf], sbase + OFF_ALO + aOff[mf] + kByte);
            }
            #pragma unroll
            for (int h = 0; h < 2; ++h) {
                ldsm_x4(bh[h], sbase + OFF_BHI + bOff[h] + kByte);
                ldsm_x4(bl[h], sbase + OFF_BLO + bOff[h] + kByte);
            }
            #pragma unroll
            for (int mf = 0; mf < 2; ++mf) {
                #pragma unroll
                for (int nf = 0; nf < 4; ++nf) {
                    const int g = nf >> 1, s = (nf & 1) * 2;
                    mma16816(acc[mf][nf], ah[mf], bh[g][s], bh[g][s + 1]); // hi*hi
                    mma16816(acc[mf][nf], ah[mf], bl[g][s], bl[g][s + 1]); // hi*lo
                    mma16816(acc[mf][nf], al[mf], bh[g][s], bh[g][s + 1]); // lo*hi
                }
            }
        }
        __syncthreads();
    }

    // ---- epilogue: fragments -> global with per-region transform ----------
    const int l4 = lane >> 2;
    const int l2 = (lane & 3) * 2;
    const int region = n0 >> 8;  // mode 0: 0=q, 1=k, 2=v
    #pragma unroll
    for (int mf = 0; mf < 2; ++mf) {
        #pragma unroll
        for (int nf = 0; nf < 4; ++nf) {
            int gr = m0 + wm + mf * 16 + l4;
            int gc = n0 + wn + nf * 8 + l2;
            float r[4];
            #pragma unroll
            for (int j = 0; j < 4; ++j) {
                float v = acc[mf][nf][j];
                int col = gc + (j & 1);
                if (mode == 0) {
                    if (region == 0)      r[j] = v * __expf(b0[col]);
                    else if (region == 1) r[j] = v * __expf(b1[col - 256]);
                    else                  r[j] = __logf(v) + b2[col - 512];
                } else {
                    r[j] = __logf(v) + b0[col];
                }
            }
            *(float2*)&C[gr * ldc + gc]       = make_float2(r[0], r[1]);
            *(float2*)&C[(gr + 8) * ldc + gc] = make_float2(r[2], r[3]);
        }
    }
}

// ---------------------------------------------------------------------------
// Attention: one CTA per (b, h). p = exp(q)*exp(k); attn = p/rowsum;
// out = attn @ v (v = log(Sv)+bv already in g_Y); emit exp(out) as bf16 hi/lo.
// ---------------------------------------------------------------------------
__global__ void k_attn()
{
    __shared__ float P[64][65];
    __shared__ float V[64][68];
    __shared__ float inv[64];

    const int h = blockIdx.x;
    const int b = blockIdx.y;
    const int tid = threadIdx.x;

    for (int i = tid; i < 4096; i += 256) {
        int s = i >> 6, d = i & 63;
        const float* yr = &g_Y[(b * 64 + s) * NQKV + h * 64 + d];
        P[s][d] = yr[0] * yr[256];
    }
    for (int i = tid; i < 4096; i += 256) {
        int d = i >> 6, e = i & 63;
        V[d][e] = g_Y[(b * 64 + d) * NQKV + 512 + h * 64 + e];
    }
    __syncthreads();

    if (tid < 64) {
        float s = 0.f;
        #pragma unroll
        for (int j = 0; j < 64; ++j) s += P[tid][j];
        inv[tid] = 1.0f / s;
    }
    __syncthreads();

    const int tx = tid & 15;
    const int ty = tid >> 4;
    float acc[4][4] = {};

    #pragma unroll 4
    for (int d = 0; d < 64; ++d) {
        float p0 = P[4 * ty + 0][d];
        float p1 = P[4 * ty + 1][d];
        float p2 = P[4 * ty + 2][d];
        float p3 = P[4 * ty + 3][d];
        float4 v4 = *(const float4*)&V[d][4 * tx];
        acc[0][0] += p0 * v4.x; acc[0][1] += p0 * v4.y;
        acc[0][2] += p0 * v4.z; acc[0][3] += p0 * v4.w;
        acc[1][0] += p1 * v4.x; acc[1][1] += p1 * v4.y;
        acc[1][2] += p1 * v4.z; acc[1][3] += p1 * v4.w;
        acc[2][0] += p2 * v4.x; acc[2][1] += p2 * v4.y;
        acc[2][2] += p2 * v4.z; acc[2][3] += p2 * v4.w;
        acc[3][0] += p3 * v4.x; acc[3][1] += p3 * v4.y;
        acc[3][2] += p3 * v4.z; acc[3][3] += p3 * v4.w;
    }

    #pragma unroll
    for (int r = 0; r < 4; ++r) {
        float iv = inv[4 * ty + r];
        int grow = b * 64 + 4 * ty + r;
        #pragma unroll
        for (int c = 0; c < 4; ++c) {
            float eo = __expf(acc[r][c] * iv);
            __nv_bfloat16 hb = __float2bfloat16(eo);
            int gi = grow * EDIM + h * 64 + 4 * tx + c;
            g_EOhi[gi] = hb;
            g_EOlo[gi] = __float2bfloat16(eo - __bfloat162float(hb));
        }
    }
}

// ---------------------------------------------------------------------------
extern "C" void kernel_launch(void* const* d_in, const int* in_sizes, int n_in,
                              void* d_out, int out_size)
{
    const float* x  = (const float*)d_in[0];
    const float* Wq = (const float*)d_in[1];
    const float* bq = (const float*)d_in[2];
    const float* Wk = (const float*)d_in[3];
    const float* bk = (const float*)d_in[4];
    const float* Wv = (const float*)d_in[5];
    const float* bv = (const float*)d_in[6];
    const float* Wo = (const float*)d_in[7];
    const float* bo = (const float*)d_in[8];
    float* out = (float*)d_out;

    static bool attr_set = false;
    if (!attr_set) {
        cudaFuncSetAttribute(k_tgemm, cudaFuncAttributeMaxDynamicSharedMemorySize, SM_TOT);
        attr_set = true;
    }

    float* Y = nullptr; cudaGetSymbolAddress((void**)&Y, g_Y);
    __nv_bfloat16 *Ahi, *Alo, *Bhi, *Blo, *Chi, *Clo, *EOhi, *EOlo;
    cudaGetSymbolAddress((void**)&Ahi, g_Ahi);
    cudaGetSymbolAddress((void**)&Alo, g_Alo);
    cudaGetSymbolAddress((void**)&Bhi, g_Bhi);
    cudaGetSymbolAddress((void**)&Blo, g_Blo);
    cudaGetSymbolAddress((void**)&Chi, g_Chi);
    cudaGetSymbolAddress((void**)&Clo, g_Clo);
    cudaGetSymbolAddress((void**)&EOhi, g_EOhi);
    cudaGetSymbolAddress((void**)&EOlo, g_EOlo);

    // 1. exp + bf16 hi/lo split of all operands (786432 elems)
    k_prep<<<3072, 256>>>(x, Wq, Wk, Wv, Wo);

    // 2. fused QKV GEMM on tensor pipe
    {
        dim3 grid(NQKV / 64, NROWS / 128);  // (12, 16)
        k_tgemm<<<grid, 256, SM_TOT>>>(Ahi, Alo, Bhi, Blo, Y, NQKV, bq, bk, bv, 0);
    }

    // 3. attention per (b, h)
    {
        dim3 grid(NH, 32);
        k_attn<<<grid, 256>>>();
    }

    // 4. output projection: out = log(EO @ exp(Wo)^T-layout) + bo
    {
        dim3 grid(EDIM / 64, NROWS / 128);  // (4, 16)
        k_tgemm<<<grid, 256, SM_TOT>>>(EOhi, EOlo, Chi, Clo, out, EDIM, bo, nullptr, nullptr, 1);
    }
}

// round 5
// speedup vs baseline: 1.6034x; 1.3084x over previous
#include <cuda_runtime.h>
#include <cuda_bf16.h>
#include <cstdint>
#include <math.h>

// Problem constants: B=32, S=64, E=256, H=4, D=64
#define NROWS 2048
#define EDIM  256
#define NQKV  768
#define NH    4

// ---------------- scratch (__device__ globals, no allocs) -------------------
__device__ __nv_bfloat16 g_Ahi[NROWS * EDIM], g_Alo[NROWS * EDIM];   // exp(x) split
__device__ __nv_bfloat16 g_Bhi[NQKV * EDIM],  g_Blo[NQKV * EDIM];    // exp(Wqkv) [n][k]
__device__ __nv_bfloat16 g_Chi[EDIM * EDIM],  g_Clo[EDIM * EDIM];    // exp(Wo)   [n][k]
__device__ __nv_bfloat16 g_EOhi[NROWS * EDIM], g_EOlo[NROWS * EDIM]; // exp(attn out)
__device__ float g_Y[NROWS * NQKV];  // q,k: sum*exp(bias); v: log(sum)+bv

// ---------------- helpers (base ISA only — sm_103 non-variant) --------------
__device__ __forceinline__ uint32_t smem_u32(const void* p) {
    uint32_t a;
    asm("{ .reg .u64 t; cvta.to.shared.u64 t, %1; cvt.u32.u64 %0, t; }"
        : "=r"(a) : "l"(p));
    return a;
}
__device__ __forceinline__ void ldsm_x4(uint32_t* r, uint32_t addr) {
    asm volatile("ldmatrix.sync.aligned.m8n8.x4.shared.b16 {%0,%1,%2,%3}, [%4];"
                 : "=r"(r[0]), "=r"(r[1]), "=r"(r[2]), "=r"(r[3]) : "r"(addr));
}
__device__ __forceinline__ void mma16816(float* d, const uint32_t* a,
                                         uint32_t b0, uint32_t b1) {
    asm volatile(
        "mma.sync.aligned.m16n8k16.row.col.f32.bf16.bf16.f32 "
        "{%0,%1,%2,%3}, {%4,%5,%6,%7}, {%8,%9}, {%0,%1,%2,%3};"
        : "+f"(d[0]), "+f"(d[1]), "+f"(d[2]), "+f"(d[3])
        : "r"(a[0]), "r"(a[1]), "r"(a[2]), "r"(a[3]), "r"(b0), "r"(b1));
}
__device__ __forceinline__ void cp16(uint32_t s, const void* g) {
    asm volatile("cp.async.cg.shared.global [%0], [%1], 16;" :: "r"(s), "l"(g));
}
#define CP_COMMIT() asm volatile("cp.async.commit_group;" ::: "memory")
#define CP_WAIT1()  asm volatile("cp.async.wait_group 1;" ::: "memory")
#define CP_WAIT0()  asm volatile("cp.async.wait_group 0;" ::: "memory")

// ---------------------------------------------------------------------------
// Prep: exp() everything, split into bf16 hi/lo pairs. float4-vectorized.
// ---------------------------------------------------------------------------
__global__ void k_prep(const float* __restrict__ x,
                       const float* __restrict__ Wq, const float* __restrict__ Wk,
                       const float* __restrict__ Wv, const float* __restrict__ Wo)
{
    int q = blockIdx.x * blockDim.x + threadIdx.x;   // quad index
    const float* src; __nv_bfloat16 *hi, *lo; int idx;
    if (q < (NROWS * EDIM) / 4) {
        idx = q * 4; src = &x[idx]; hi = g_Ahi; lo = g_Alo;
    } else if (q < (NROWS * EDIM + NQKV * EDIM) / 4) {
        idx = q * 4 - NROWS * EDIM;
        int n = idx / EDIM, k = idx - n * EDIM;
        const float* W = (n < 256) ? Wq : ((n < 512) ? Wk : Wv);
        src = &W[(n & 255) * EDIM + k]; hi = g_Bhi; lo = g_Blo;
    } else {
        idx = q * 4 - NROWS * EDIM - NQKV * EDIM;
        src = &Wo[idx]; hi = g_Chi; lo = g_Clo;
    }
    float4 v4 = *(const float4*)src;
    __nv_bfloat16 h[4], l[4];
    float vv[4] = {__expf(v4.x), __expf(v4.y), __expf(v4.z), __expf(v4.w)};
    #pragma unroll
    for (int j = 0; j < 4; ++j) {
        h[j] = __float2bfloat16(vv[j]);
        l[j] = __float2bfloat16(vv[j] - __bfloat162float(h[j]));
    }
    *(uint2*)&hi[idx] = *(uint2*)h;
    *(uint2*)&lo[idx] = *(uint2*)l;
}

// ---------------------------------------------------------------------------
// bf16x3 GEMM via mma.sync, cp.async double-buffered.
//   C[m,n] = sum_k A[m,k]*B[n,k], fp32 accum. CTA 64x64, 128 thr, K=256 in 4x64.
//   mode 0 epilogue: n<256 -> acc*exp(bq), n<512 -> acc*exp(bk), else log+bv
//   mode 1 epilogue: log(acc)+bo
// ---------------------------------------------------------------------------
#define LDT 72                         // padded row stride (bf16), 144 B
#define ARR_BYTES (64 * LDT * 2)       // 9216 per array
#define STG_BYTES (4 * ARR_BYTES)      // 36864 per stage: Ahi,Alo,Bhi,Blo
#define SM_TOT    (2 * STG_BYTES)      // 73728

__global__ void __launch_bounds__(128) k_tgemm(
    const __nv_bfloat16* __restrict__ Ahi, const __nv_bfloat16* __restrict__ Alo,
    const __nv_bfloat16* __restrict__ Bhi, const __nv_bfloat16* __restrict__ Blo,
    float* __restrict__ C, int ldc,
    const float* __restrict__ b0, const float* __restrict__ b1,
    const float* __restrict__ b2, int mode)
{
    extern __shared__ char smem[];
    const uint32_t sbase = smem_u32(smem);

    const int tid  = threadIdx.x;
    const int lane = tid & 31;
    const int warp = tid >> 5;
    const int wm   = (warp & 1) * 32;
    const int wn   = (warp >> 1) * 32;
    const int m0 = blockIdx.y * 64;
    const int n0 = blockIdx.x * 64;

    // per-thread fill coordinates (512 16B-chunks per array, 4 per thread)
    // c = tid + 128*i : r = c>>3 (0..63), k8 = (c&7)*8
    // ldmatrix base byte-offsets within an array
    uint32_t aOff[2], bOff[2];
    #pragma unroll
    for (int mf = 0; mf < 2; ++mf)
        aOff[mf] = ((wm + mf * 16 + (lane & 15)) * LDT + (lane >> 4) * 8) * 2;
    #pragma unroll
    for (int h = 0; h < 2; ++h)
        bOff[h] = ((wn + h * 16 + (lane >> 4) * 8 + (lane & 7)) * LDT
                   + ((lane >> 3) & 1) * 8) * 2;

    float acc[2][4][4];
    #pragma unroll
    for (int mf = 0; mf < 2; ++mf)
        #pragma unroll
        for (int nf = 0; nf < 4; ++nf)
            #pragma unroll
            for (int j = 0; j < 4; ++j) acc[mf][nf][j] = 0.f;

    // ---- prefetch helper (macro-ish lambda) -------------------------------
    auto prefetch = [&](int kc, int stg) {
        const int kb = kc * 64;
        const uint32_t s0 = sbase + stg * STG_BYTES;
        #pragma unroll
        for (int i = 0; i < 4; ++i) {
            int c = tid + 128 * i;
            int r = c >> 3, k8 = (c & 7) * 8;
            uint32_t so = (r * LDT + k8) * 2;
            cp16(s0 + 0 * ARR_BYTES + so, &Ahi[(m0 + r) * EDIM + kb + k8]);
            cp16(s0 + 1 * ARR_BYTES + so, &Alo[(m0 + r) * EDIM + kb + k8]);
            cp16(s0 + 2 * ARR_BYTES + so, &Bhi[(n0 + r) * EDIM + kb + k8]);
            cp16(s0 + 3 * ARR_BYTES + so, &Blo[(n0 + r) * EDIM + kb + k8]);
        }
        CP_COMMIT();
    };

    prefetch(0, 0);

    for (int kc = 0; kc < 4; ++kc) {
        if (kc < 3) prefetch(kc + 1, (kc + 1) & 1);
        if (kc < 3) CP_WAIT1(); else CP_WAIT0();
        __syncthreads();

        const uint32_t s0 = sbase + (kc & 1) * STG_BYTES;
        #pragma unroll
        for (int ks = 0; ks < 4; ++ks) {
            const uint32_t kByte = ks * 32;  // 16 bf16
            uint32_t ah[2][4], al[2][4], bh[2][4], bl[2][4];
            #pragma unroll
            for (int mf = 0; mf < 2; ++mf) {
                ldsm_x4(ah[mf], s0 + 0 * ARR_BYTES + aOff[mf] + kByte);
                ldsm_x4(al[mf], s0 + 1 * ARR_BYTES + aOff[mf] + kByte);
            }
            #pragma unroll
            for (int h = 0; h < 2; ++h) {
                ldsm_x4(bh[h], s0 + 2 * ARR_BYTES + bOff[h] + kByte);
                ldsm_x4(bl[h], s0 + 3 * ARR_BYTES + bOff[h] + kByte);
            }
            #pragma unroll
            for (int mf = 0; mf < 2; ++mf) {
                #pragma unroll
                for (int nf = 0; nf < 4; ++nf) {
                    const int g = nf >> 1, s = (nf & 1) * 2;
                    mma16816(acc[mf][nf], ah[mf], bh[g][s], bh[g][s + 1]); // hi*hi
                    mma16816(acc[mf][nf], ah[mf], bl[g][s], bl[g][s + 1]); // hi*lo
                    mma16816(acc[mf][nf], al[mf], bh[g][s], bh[g][s + 1]); // lo*hi
                }
            }
        }
        __syncthreads();
    }

    // ---- epilogue ---------------------------------------------------------
    const int l4 = lane >> 2;
    const int l2 = (lane & 3) * 2;
    const int region = n0 >> 8;  // mode 0: 0=q, 1=k, 2=v
    #pragma unroll
    for (int mf = 0; mf < 2; ++mf) {
        #pragma unroll
        for (int nf = 0; nf < 4; ++nf) {
            int gr = m0 + wm + mf * 16 + l4;
            int gc = n0 + wn + nf * 8 + l2;
            float r[4];
            #pragma unroll
            for (int j = 0; j < 4; ++j) {
                float v = acc[mf][nf][j];
                int col = gc + (j & 1);
                if (mode == 0) {
                    if (region == 0)      r[j] = v * __expf(b0[col]);
                    else if (region == 1) r[j] = v * __expf(b1[col - 256]);
                    else                  r[j] = __logf(v) + b2[col - 512];
                } else {
                    r[j] = __logf(v) + b0[col];
                }
            }
            *(float2*)&C[gr * ldc + gc]       = make_float2(r[0], r[1]);
            *(float2*)&C[(gr + 8) * ldc + gc] = make_float2(r[2], r[3]);
        }
    }
}

// ---------------------------------------------------------------------------
// Attention: one CTA per (b, h). p = exp(q)*exp(k); attn = p/rowsum;
// out = attn @ v (v = log(Sv)+bv already in g_Y); emit exp(out) as bf16 hi/lo.
// ---------------------------------------------------------------------------
__global__ void k_attn()
{
    __shared__ float P[64][65];
    __shared__ float V[64][68];
    __shared__ float inv[64];

    const int h = blockIdx.x;
    const int b = blockIdx.y;
    const int tid = threadIdx.x;

    for (int i = tid; i < 4096; i += 256) {
        int s = i >> 6, d = i & 63;
        const float* yr = &g_Y[(b * 64 + s) * NQKV + h * 64 + d];
        P[s][d] = yr[0] * yr[256];
    }
    for (int i = tid; i < 4096; i += 256) {
        int d = i >> 6, e = i & 63;
        V[d][e] = g_Y[(b * 64 + d) * NQKV + 512 + h * 64 + e];
    }
    __syncthreads();

    if (tid < 64) {
        float s = 0.f;
        #pragma unroll
        for (int j = 0; j < 64; ++j) s += P[tid][j];
        inv[tid] = 1.0f / s;
    }
    __syncthreads();

    const int tx = tid & 15;
    const int ty = tid >> 4;
    float acc[4][4] = {};

    #pragma unroll 4
    for (int d = 0; d < 64; ++d) {
        float p0 = P[4 * ty + 0][d];
        float p1 = P[4 * ty + 1][d];
        float p2 = P[4 * ty + 2][d];
        float p3 = P[4 * ty + 3][d];
        float4 v4 = *(const float4*)&V[d][4 * tx];
        acc[0][0] += p0 * v4.x; acc[0][1] += p0 * v4.y;
        acc[0][2] += p0 * v4.z; acc[0][3] += p0 * v4.w;
        acc[1][0] += p1 * v4.x; acc[1][1] += p1 * v4.y;
        acc[1][2] += p1 * v4.z; acc[1][3] += p1 * v4.w;
        acc[2][0] += p2 * v4.x; acc[2][1] += p2 * v4.y;
        acc[2][2] += p2 * v4.z; acc[2][3] += p2 * v4.w;
        acc[3][0] += p3 * v4.x; acc[3][1] += p3 * v4.y;
        acc[3][2] += p3 * v4.z; acc[3][3] += p3 * v4.w;
    }

    #pragma unroll
    for (int r = 0; r < 4; ++r) {
        float iv = inv[4 * ty + r];
        int grow = b * 64 + 4 * ty + r;
        #pragma unroll
        for (int c = 0; c < 4; ++c) {
            float eo = __expf(acc[r][c] * iv);
            __nv_bfloat16 hb = __float2bfloat16(eo);
            int gi = grow * EDIM + h * 64 + 4 * tx + c;
            g_EOhi[gi] = hb;
            g_EOlo[gi] = __float2bfloat16(eo - __bfloat162float(hb));
        }
    }
}

// ---------------------------------------------------------------------------
extern "C" void kernel_launch(void* const* d_in, const int* in_sizes, int n_in,
                              void* d_out, int out_size)
{
    const float* x  = (const float*)d_in[0];
    const float* Wq = (const float*)d_in[1];
    const float* bq = (const float*)d_in[2];
    const float* Wk = (const float*)d_in[3];
    const float* bk = (const float*)d_in[4];
    const float* Wv = (const float*)d_in[5];
    const float* bv = (const float*)d_in[6];
    const float* Wo = (const float*)d_in[7];
    const float* bo = (const float*)d_in[8];
    float* out = (float*)d_out;

    static bool attr_set = false;
    if (!attr_set) {
        cudaFuncSetAttribute(k_tgemm, cudaFuncAttributeMaxDynamicSharedMemorySize, SM_TOT);
        attr_set = true;
    }

    float* Y = nullptr; cudaGetSymbolAddress((void**)&Y, g_Y);
    __nv_bfloat16 *Ahi, *Alo, *Bhi, *Blo, *Chi, *Clo, *EOhi, *EOlo;
    cudaGetSymbolAddress((void**)&Ahi, g_Ahi);
    cudaGetSymbolAddress((void**)&Alo, g_Alo);
    cudaGetSymbolAddress((void**)&Bhi, g_Bhi);
    cudaGetSymbolAddress((void**)&Blo, g_Blo);
    cudaGetSymbolAddress((void**)&Chi, g_Chi);
    cudaGetSymbolAddress((void**)&Clo, g_Clo);
    cudaGetSymbolAddress((void**)&EOhi, g_EOhi);
    cudaGetSymbolAddress((void**)&EOlo, g_EOlo);

    // 1. exp + bf16 hi/lo split of all operands (786432 elems / 4 per thread)
    k_prep<<<768, 256>>>(x, Wq, Wk, Wv, Wo);

    // 2. fused QKV GEMM on tensor pipe (384 CTAs)
    {
        dim3 grid(NQKV / 64, NROWS / 64);  // (12, 32)
        k_tgemm<<<grid, 128, SM_TOT>>>(Ahi, Alo, Bhi, Blo, Y, NQKV, bq, bk, bv, 0);
    }

    // 3. attention per (b, h)
    {
        dim3 grid(NH, 32);
        k_attn<<<grid, 256>>>();
    }

    // 4. output projection (128 CTAs): out = log(EO @ exp(Wo)) + bo
    {
        dim3 grid(EDIM / 64, NROWS / 64);  // (4, 32)
        k_tgemm<<<grid, 128, SM_TOT>>>(EOhi, EOlo, Chi, Clo, out, EDIM, bo, nullptr, nullptr, 1);
    }
}